// round 1
// baseline (speedup 1.0000x reference)
#include <cuda_runtime.h>

#define BB 8
#define TT 2048
#define CC 1024
#define HH 64
#define MM (BB*TT)   // 16384

// scratch for q, k, v (4 MB each) — __device__ globals per allocation rules
__device__ float g_q[MM*HH];
__device__ float g_k[MM*HH];
__device__ float g_v[MM*HH];

// ---------------------------------------------------------------------------
// Kernel 1: fused QKV projection. out[m][n] = sum_k x[m][k] * W[k][n]
// M=16384, K=1024, N=64.  BM=64, BN=64(=H), BK=16. 256 threads, 4x4/thread.
// blockIdx.y in {0,1,2} selects (Wq,g_q) / (Wk,g_k) / (Wv,g_v).
// ---------------------------------------------------------------------------
__global__ __launch_bounds__(256) void qkv_gemm(
    const float* __restrict__ x,
    const float* __restrict__ Wq,
    const float* __restrict__ Wk,
    const float* __restrict__ Wv)
{
    __shared__ float As[16][68];  // [k][m], padded (68: float4-aligned, 2-way max)
    __shared__ float Bs[16][64];  // [k][n]

    const float* W  = (blockIdx.y == 0) ? Wq : ((blockIdx.y == 1) ? Wk : Wv);
    float*       out = (blockIdx.y == 0) ? g_q : ((blockIdx.y == 1) ? g_k : g_v);

    const int m0  = blockIdx.x * 64;
    const int tid = threadIdx.x;
    const int tx  = tid & 15;          // 0..15 -> output cols tx*4..+3
    const int ty  = tid >> 4;          // 0..15 -> output rows ty*4..+3

    // A-load mapping: thread -> (row, quad of 4 floats)
    const int lrow  = tid >> 2;        // 0..63
    const int lquad = tid & 3;         // 0..3
    // B-load mapping: thread -> (k row, quad of 4 floats along n)
    const int bk = tid >> 4;           // 0..15
    const int bq = tid & 15;           // 0..15

    float acc[4][4] = {};

    for (int k0 = 0; k0 < CC; k0 += 16) {
        float4 av = *(const float4*)&x[(size_t)(m0 + lrow) * CC + k0 + lquad * 4];
        As[lquad*4 + 0][lrow] = av.x;
        As[lquad*4 + 1][lrow] = av.y;
        As[lquad*4 + 2][lrow] = av.z;
        As[lquad*4 + 3][lrow] = av.w;
        *(float4*)&Bs[bk][bq*4] = *(const float4*)&W[(size_t)(k0 + bk) * HH + bq * 4];
        __syncthreads();

        #pragma unroll
        for (int k = 0; k < 16; k++) {
            float4 a4 = *(const float4*)&As[k][ty*4];
            float4 b4 = *(const float4*)&Bs[k][tx*4];
            float a[4] = {a4.x, a4.y, a4.z, a4.w};
            float b[4] = {b4.x, b4.y, b4.z, b4.w};
            #pragma unroll
            for (int i = 0; i < 4; i++)
                #pragma unroll
                for (int j = 0; j < 4; j++)
                    acc[i][j] += a[i] * b[j];
        }
        __syncthreads();
    }

    #pragma unroll
    for (int i = 0; i < 4; i++) {
        float4 v = make_float4(acc[i][0], acc[i][1], acc[i][2], acc[i][3]);
        *(float4*)&out[(size_t)(m0 + ty*4 + i) * HH + tx*4] = v;
    }
}

// ---------------------------------------------------------------------------
// Kernel 2: causal flash attention with online softmax.
// grid = (T/64, B). 64 threads/block: thread t owns query row q0+t.
// q[64], o[64] in registers; K/V tiles (64x64) in shared (broadcast reads);
// scores in shared transposed Ps[j][tid] (conflict-free, no padding needed).
// Static smem = 3 * 16 KB = 48 KB exactly.
// ---------------------------------------------------------------------------
__global__ __launch_bounds__(64) void attn(float* __restrict__ out)
{
    __shared__ float Ks[64][64];
    __shared__ float Vs[64][64];
    __shared__ float Ps[64][64];   // Ps[key j][query thread]

    const int b   = blockIdx.y;
    // launch heavy (late-diagonal) tiles first to fix causal imbalance
    const int qt  = (gridDim.x - 1) - blockIdx.x;
    const int q0  = qt * 64;
    const int tid = threadIdx.x;          // 0..63
    const int row = q0 + tid;             // absolute query row in [0,T)
    const float scale = 0.03125f;         // C^-0.5 = 1/32

    // load my query row, pre-scaled
    float q[64];
    {
        const float* qrow = &g_q[((size_t)b * TT + row) * HH];
        #pragma unroll
        for (int d = 0; d < 64; d += 4) {
            float4 v = *(const float4*)&qrow[d];
            q[d+0] = v.x * scale; q[d+1] = v.y * scale;
            q[d+2] = v.z * scale; q[d+3] = v.w * scale;
        }
    }

    float o[64];
    #pragma unroll
    for (int d = 0; d < 64; d++) o[d] = 0.f;
    float m = -1e30f, l = 0.f;

    const int nTiles = qt + 1;
    for (int t = 0; t < nTiles; t++) {
        const int k0 = t * 64;
        // cooperative coalesced load of K, V tiles (row-major copy)
        {
            const float4* kb = (const float4*)&g_k[((size_t)b * TT + k0) * HH];
            const float4* vb = (const float4*)&g_v[((size_t)b * TT + k0) * HH];
            float4* ks = (float4*)&Ks[0][0];
            float4* vs = (float4*)&Vs[0][0];
            #pragma unroll
            for (int i = 0; i < 16; i++) {
                int idx = i * 64 + tid;
                ks[idx] = kb[idx];
                vs[idx] = vb[idx];
            }
        }
        __syncthreads();

        // scores s_j = q . K_j (causal-masked), tile max
        float mt = -1e30f;
        for (int j = 0; j < 64; j++) {
            float s;
            if (k0 + j > row) {
                s = -1e30f;
            } else {
                float a0 = 0.f, a1 = 0.f, a2 = 0.f, a3 = 0.f;
                const float4* kr = (const float4*)&Ks[j][0];
                #pragma unroll
                for (int d4 = 0; d4 < 16; d4++) {
                    float4 kv = kr[d4];
                    a0 += q[d4*4+0] * kv.x;
                    a1 += q[d4*4+1] * kv.y;
                    a2 += q[d4*4+2] * kv.z;
                    a3 += q[d4*4+3] * kv.w;
                }
                s = (a0 + a1) + (a2 + a3);
            }
            Ps[j][tid] = s;
            mt = fmaxf(mt, s);
        }

        // online softmax rescale
        const float mnew = fmaxf(m, mt);
        const float corr = __expf(m - mnew);
        l *= corr;
        #pragma unroll
        for (int d = 0; d < 64; d++) o[d] *= corr;

        // accumulate p.V
        for (int j = 0; j < 64; j++) {
            float p = __expf(Ps[j][tid] - mnew);
            l += p;
            const float4* vr = (const float4*)&Vs[j][0];
            #pragma unroll
            for (int d4 = 0; d4 < 16; d4++) {
                float4 vv = vr[d4];
                o[d4*4+0] += p * vv.x;
                o[d4*4+1] += p * vv.y;
                o[d4*4+2] += p * vv.z;
                o[d4*4+3] += p * vv.w;
            }
        }
        m = mnew;
        __syncthreads();
    }

    const float inv = 1.f / l;
    float* orow = &out[((size_t)b * TT + row) * HH];
    #pragma unroll
    for (int d = 0; d < 64; d += 4) {
        float4 v = make_float4(o[d]*inv, o[d+1]*inv, o[d+2]*inv, o[d+3]*inv);
        *(float4*)&orow[d] = v;
    }
}

// ---------------------------------------------------------------------------
extern "C" void kernel_launch(void* const* d_in, const int* in_sizes, int n_in,
                              void* d_out, int out_size)
{
    const float* x  = (const float*)d_in[0];
    const float* Wq = (const float*)d_in[1];
    const float* Wk = (const float*)d_in[2];
    const float* Wv = (const float*)d_in[3];
    float* out = (float*)d_out;

    dim3 g1(MM / 64, 3);
    qkv_gemm<<<g1, 256>>>(x, Wq, Wk, Wv);

    dim3 g2(TT / 64, BB);
    attn<<<g2, 64>>>(out);
}